// round 10
// baseline (speedup 1.0000x reference)
#include <cuda_runtime.h>
#include <cuda_bf16.h>
#include <math.h>
#include <stdint.h>

#define KD    512
#define KH    8
#define KDH   64
#define KHID  2730
#define KB    4
#define KNS   4096
#define KNT   512
#define SROWS (KB*KNS)
#define TROWS (KB*KNT)
#define KPAD  2752
#define NPAD  5504

typedef __nv_bfloat16 bf;
#define DEVB(n, s) __device__ __align__(16) bf n[s]
#define DEVF(n, s) __device__ __align__(16) float n[s]

DEVB(LsQh,SROWS*KD); DEVB(LsQl,SROWS*KD);
DEVB(LtKVh,TROWS*KD);DEVB(LtKVl,TROWS*KD);
DEVB(LtQh,TROWS*KD); DEVB(LtQl,TROWS*KD);
DEVB(LsKVh,SROWS*KD);DEVB(LsKVl,SROWS*KD);
DEVB(Qsh,SROWS*KD);  DEVB(Qsl,SROWS*KD);
DEVB(Ksh,TROWS*KD);  DEVB(Ksl,TROWS*KD);
DEVB(VtSh,KB*KD*KNT);DEVB(VtSl,KB*KD*KNT);
DEVB(Qth,TROWS*KD);  DEVB(Qtl,TROWS*KD);
DEVB(Kth,SROWS*KD);  DEVB(Ktl,SROWS*KD);
DEVB(VtTh,KB*KD*KNS);DEVB(VtTl,KB*KD*KNS);
DEVB(AtSh,SROWS*KD); DEVB(AtSl,SROWS*KD);
DEVB(AtTh,TROWS*KD); DEVB(AtTl,TROWS*KD);
DEVF(SctxF,SROWS*KD);
DEVF(TctxF,TROWS*KD);
DEVF(TmeanF,KB*KD);
DEVB(Hmh,SROWS*2*KD); DEVB(Hml,SROWS*2*KD);
DEVB(Gth,(size_t)SROWS*KPAD); DEVB(Gtl,(size_t)SROWS*KPAD);
DEVB(WqkvSh,3*KD*KD); DEVB(WqkvSl,3*KD*KD);
DEVB(WqkvTh,3*KD*KD); DEVB(WqkvTl,3*KD*KD);
DEVB(WcSh,KD*KD); DEVB(WcSl,KD*KD);        // combined Wp@Wo (spatial)
DEVB(WcTh,KD*KD); DEVB(WcTl,KD*KD);        // combined (temporal)
DEVF(BcS,KD); DEVF(BcT,KD);                // combined biases
DEVB(Winh,NPAD*2*KD); DEVB(Winl,NPAD*2*KD);
DEVB(Wouth,KD*KPAD);  DEVB(Woutl,KD*KPAD);
DEVF(BinP,NPAD);

__device__ __forceinline__ void splitw(float x, bf* H, bf* L){
    bf h = __float2bfloat16(x); *H = h; *L = __float2bfloat16(x - __bfloat162float(h));
}
__device__ __forceinline__ void mma_bf(float* c, const uint32_t* a, const uint32_t* b){
    asm volatile("mma.sync.aligned.m16n8k16.row.col.f32.bf16.bf16.f32 "
        "{%0,%1,%2,%3}, {%4,%5,%6,%7}, {%8,%9}, {%0,%1,%2,%3};"
        : "+f"(c[0]),"+f"(c[1]),"+f"(c[2]),"+f"(c[3])
        : "r"(a[0]),"r"(a[1]),"r"(a[2]),"r"(a[3]), "r"(b[0]),"r"(b[1]));
}
__device__ __forceinline__ uint32_t cvsm(const void* p){
    uint32_t a; asm("{ .reg .u64 t; cvta.to.shared.u64 t, %1; cvt.u32.u64 %0, t; }":"=r"(a):"l"(p)); return a;
}
__device__ __forceinline__ void ldm_x4(uint32_t* r, uint32_t a){
    asm volatile("ldmatrix.sync.aligned.m8n8.x4.shared.b16 {%0,%1,%2,%3}, [%4];"
        : "=r"(r[0]),"=r"(r[1]),"=r"(r[2]),"=r"(r[3]) : "r"(a));
}
#define CPA(d, s) asm volatile("cp.async.cg.shared.global [%0], [%1], 16;"::"r"(d),"l"(s):"memory")
#define CPA_COMMIT() asm volatile("cp.async.commit_group;":::"memory")
#define CPA_WAIT1() asm volatile("cp.async.wait_group 1;":::"memory")
#define CPA_WAIT0() asm volatile("cp.async.wait_group 0;":::"memory")

__device__ __forceinline__ float brSum(float v){
    __shared__ float sh[33]; __syncthreads();
    int ln = threadIdx.x&31, w = threadIdx.x>>5;
    #pragma unroll
    for(int o=16;o;o>>=1) v += __shfl_xor_sync(~0u,v,o);
    if(!ln) sh[w]=v; __syncthreads();
    if(!w){ int nw=blockDim.x>>5; float r=(ln<nw)?sh[ln]:0.f;
        #pragma unroll
        for(int o=16;o;o>>=1) r += __shfl_xor_sync(~0u,r,o);
        if(!ln) sh[32]=r; }
    __syncthreads(); return sh[32];
}

// ---------------- elementwise ----------------
// One stats pass, two (g,b) applications (both LNs read the same x).
__global__ void __launch_bounds__(128)
ln2_k(const float* __restrict__ x,
      const float* __restrict__ g1, const float* __restrict__ b1,
      const float* __restrict__ g2, const float* __restrict__ b2,
      bf* __restrict__ y1h, bf* __restrict__ y1l,
      bf* __restrict__ y2h, bf* __restrict__ y2l)
{
    long row = blockIdx.x;
    const float* px = x + row*KD;
    int t = threadIdx.x;
    float v[4]; float s=0.f;
    #pragma unroll
    for(int i=0;i<4;i++){ v[i]=px[t+(i<<7)]; s+=v[i]; }
    s = brSum(s); float m = s*(1.f/KD);
    float q=0.f;
    #pragma unroll
    for(int i=0;i<4;i++){ float d=v[i]-m; q+=d*d; }
    q = brSum(q); float inv = rsqrtf(q*(1.f/KD)+1e-5f);
    #pragma unroll
    for(int i=0;i<4;i++){
        int c=t+(i<<7);
        float xn = (v[i]-m)*inv;
        splitw(xn*g1[c]+b1[c], y1h+row*KD+c, y1l+row*KD+c);
        splitw(xn*g2[c]+b2[c], y2h+row*KD+c, y2l+row*KD+c);
    }
}

__global__ void __launch_bounds__(128)
mixln_k(const float* __restrict__ sc, const float* __restrict__ tm,
        const float* __restrict__ g, const float* __restrict__ b,
        bf* __restrict__ yh, bf* __restrict__ yl)
{
    int row = blockIdx.x, bb = row>>12;
    const float *ps = sc + (long)row*KD, *pm = tm + (long)bb*KD;
    bf *ph = yh + (long)row*2*KD, *pl = yl + (long)row*2*KD;
    int t = threadIdx.x;
    float v[8]; float s=0.f;
    #pragma unroll
    for(int i=0;i<8;i++){ int c=t+(i<<7); v[i]=(c<KD)?ps[c]:pm[c-KD]; s+=v[i]; }
    s = brSum(s); float m = s*(1.f/1024.f);
    float q=0.f;
    #pragma unroll
    for(int i=0;i<8;i++){ float d=v[i]-m; q+=d*d; }
    q = brSum(q); float inv = rsqrtf(q*(1.f/1024.f)+1e-5f);
    #pragma unroll
    for(int i=0;i<8;i++){ int c=t+(i<<7); splitw((v[i]-m)*inv*g[c]+b[c], ph+c, pl+c); }
}

__global__ void tmean_k(const float* __restrict__ tc, float* __restrict__ o)
{
    int i = blockIdx.x*blockDim.x + threadIdx.x;
    if(i >= KB*KD) return;
    int bb=i>>9, dd=i&511;
    const float* p = tc + (long)bb*KNT*KD + dd;
    float s=0.f;
    for(int t=0;t<KNT;t++) s += p[t*KD];
    o[i] = s*(1.f/KNT);
}

__global__ void conv_k(const float* __restrict__ s, bf* __restrict__ dh, bf* __restrict__ dl,
                       int dR, int dC, int sR, int sC)
{
    long i = (long)blockIdx.x*blockDim.x + threadIdx.x;
    if(i >= (long)dR*dC) return;
    int r = (int)(i/dC), c = (int)(i - (long)r*dC);
    float v = (r<sR && c<sC) ? s[(long)r*sC + c] : 0.f;
    splitw(v, dh+i, dl+i);
}

__global__ void convin_k(const float* __restrict__ s, bf* __restrict__ dh, bf* __restrict__ dl)
{
    long i = (long)blockIdx.x*blockDim.x + threadIdx.x;
    if(i >= (long)NPAD*2*KD) return;
    int r = (int)(i/(2*KD)), c = (int)(i - (long)r*(2*KD));
    int pair = r>>1, half = r&1;
    float v = (pair < KHID) ? s[(long)(half*KHID+pair)*(2*KD) + c] : 0.f;
    splitw(v, dh+i, dl+i);
}
__global__ void padbin_k(const float* __restrict__ s, float* __restrict__ d)
{
    int i = blockIdx.x*blockDim.x + threadIdx.x;
    if(i >= NPAD) return;
    int pair = i>>1, half = i&1;
    d[i] = (pair < KHID) ? s[half*KHID + pair] : 0.f;
}

// Wc[n,k] = sum_j Wp[n,j]*Wo[j,k]  (combined output projection), split to hi/lo
__global__ void wc_k(const float* __restrict__ Wp, const float* __restrict__ Wo,
                     bf* __restrict__ ch, bf* __restrict__ cl)
{
    int i = blockIdx.x*blockDim.x + threadIdx.x;
    if(i >= KD*KD) return;
    int n = i>>9, k = i&511;
    float s = 0.f;
    for(int j=0;j<KD;j++) s += Wp[n*KD+j]*Wo[j*KD+k];
    splitw(s, ch+i, cl+i);
}
// bc[n] = sum_j Wp[n,j]*bo[j] + bp[n]
__global__ void bc_k(const float* __restrict__ Wp, const float* __restrict__ bo,
                     const float* __restrict__ bp, float* __restrict__ bc)
{
    int n = blockIdx.x*blockDim.x + threadIdx.x;
    if(n >= KD) return;
    float s = 0.f;
    for(int j=0;j<KD;j++) s += Wp[n*KD+j]*bo[j];
    bc[n] = s + bp[n];
}

// ---------------- fused flash attention (split-bf16 HMMA) ----------------
__global__ void __launch_bounds__(256)
flash_k(const bf* __restrict__ Qh, const bf* __restrict__ Ql,
        const bf* __restrict__ Kh, const bf* __restrict__ Kl,
        const bf* __restrict__ Vh, const bf* __restrict__ Vl,
        bf* __restrict__ Oh, bf* __restrict__ Ol,
        int Nq, int Nk)
{
    extern __shared__ char smem[];
    const int QOFF=0, KOFF=36864, VOFF=110592, UOFF=145408, RSC=217088, RLI=217600;
    const int tid = threadIdx.x, lane = tid&31, w = tid>>5;
    const int wm = w&1, wn = w>>1;
    const int gid = lane>>2, t4 = lane&3;
    uint32_t sb = cvsm(smem);

    int z = blockIdx.z, b = z>>3, h = z&7;
    long qrow0 = (long)b*Nq + (long)blockIdx.y*128;
    const bf* qh = Qh + qrow0*KD + h*KDH;
    const bf* ql = Ql + qrow0*KD + h*KDH;
    const bf* kh = Kh + (long)b*Nk*KD + h*KDH;
    const bf* kl = Kl + (long)b*Nk*KD + h*KDH;
    const bf* vh = Vh + ((long)b*KD + h*KDH)*(long)Nk;
    const bf* vl = Vl + ((long)b*KD + h*KDH)*(long)Nk;

    #pragma unroll
    for(int i=0;i<4;i++){
        int wd = tid + (i<<8); int r = wd>>3, wi = wd&7;
        CPA(sb + QOFF + r*144 + wi*16,         qh + (long)r*KD + wi*8);
        CPA(sb + QOFF + 18432 + r*144 + wi*16, ql + (long)r*KD + wi*8);
    }
    CPA_COMMIT();

    int NKB = Nk >> 7;

    auto loadK = [&](int kb){
        uint32_t base = sb + KOFF + (uint32_t)(kb&1)*36864u;
        const bf* sh_ = kh + (long)kb*128*KD;
        const bf* sl_ = kl + (long)kb*128*KD;
        #pragma unroll
        for(int i=0;i<4;i++){
            int wd = tid + (i<<8); int r = wd>>3, wi = wd&7;
            CPA(base + r*144 + wi*16,         sh_ + (long)r*KD + wi*8);
            CPA(base + 18432 + r*144 + wi*16, sl_ + (long)r*KD + wi*8);
        }
        CPA_COMMIT();
    };
    auto loadV = [&](int kb){
        #pragma unroll
        for(int i=0;i<4;i++){
            int wd = tid + (i<<8); int r = wd>>4, wi = wd&15;
            CPA(sb + VOFF + r*272 + wi*16,         vh + (long)r*Nk + kb*128 + wi*8);
            CPA(sb + VOFF + 17408 + r*272 + wi*16, vl + (long)r*Nk + kb*128 + wi*8);
        }
        CPA_COMMIT();
    };
    loadK(0); loadV(0);

    float m0 = -1e30f, l0 = 0.f;
    float occ[8][4];
    #pragma unroll
    for(int j=0;j<8;j++){ occ[j][0]=0.f; occ[j][1]=0.f; occ[j][2]=0.f; occ[j][3]=0.f; }

    for(int kb=0; kb<NKB; kb++){
        CPA_WAIT0();
        __syncthreads();
        uint32_t Kb = sb + KOFF + (uint32_t)(kb&1)*36864u;

        float cc[4][4][4];
        #pragma unroll
        for(int i=0;i<4;i++)
            #pragma unroll
            for(int j=0;j<4;j++){ cc[i][j][0]=0.f; cc[i][j][1]=0.f; cc[i][j][2]=0.f; cc[i][j][3]=0.f; }
        #pragma unroll
        for(int kc=0;kc<4;kc++){
            uint32_t bh_[4][2], bl_[4][2];
            #pragma unroll
            for(int jp=0;jp<2;jp++){
                int nr = wn*32 + jp*16 + (lane&7) + (((lane>>4)&1)<<3);
                uint32_t cb = (uint32_t)(((lane>>3)&1)<<4);
                uint32_t ad = Kb + (uint32_t)(nr*144) + (uint32_t)(kc*32) + cb;
                ldm_x4(&bh_[2*jp][0], ad);
                ldm_x4(&bl_[2*jp][0], ad + 18432u);
            }
            #pragma unroll
            for(int mt=0;mt<4;mt++){
                int ar = wm*64 + mt*16 + (lane&15);
                uint32_t cb = (uint32_t)(((lane>>4)&1)<<4);
                uint32_t ad = sb + QOFF + (uint32_t)(ar*144) + (uint32_t)(kc*32) + cb;
                uint32_t ah[4], al[4];
                ldm_x4(ah, ad);
                ldm_x4(al, ad + 18432u);
                #pragma unroll
                for(int j=0;j<4;j++){
                    mma_bf(cc[mt][j], ah, bh_[j]);
                    mma_bf(cc[mt][j], ah, bl_[j]);
                    mma_bf(cc[mt][j], al, bh_[j]);
                }
            }
        }
        #pragma unroll
        for(int mt=0;mt<4;mt++)
            #pragma unroll
            for(int j=0;j<4;j++){
                int col = wn*32 + j*8 + t4*2;
                int r0 = wm*64 + mt*16 + gid;
                float2 v0; v0.x = cc[mt][j][0]; v0.y = cc[mt][j][1];
                float2 v1; v1.x = cc[mt][j][2]; v1.y = cc[mt][j][3];
                *(float2*)(smem + UOFF + r0*560 + col*4)     = v0;
                *(float2*)(smem + UOFF + (r0+8)*560 + col*4) = v1;
            }
        if(kb+1 < NKB) loadK(kb+1);
        __syncthreads();

        {
            int row = tid>>1, hf = tid&1;
            const float* sp = (const float*)(smem + UOFF + row*560) + hf*64;
            float sv[64]; float mx = -1e30f;
            #pragma unroll
            for(int i=0;i<64;i++){ sv[i] = sp[i]*0.125f; mx = fmaxf(mx, sv[i]); }
            mx = fmaxf(mx, __shfl_xor_sync(~0u, mx, 1));
            float mnew = fmaxf(m0, mx);
            float sum = 0.f;
            #pragma unroll
            for(int i=0;i<64;i++){ sv[i] = __expf(sv[i]-mnew); sum += sv[i]; }
            sum += __shfl_xor_sync(~0u, sum, 1);
            float scl = __expf(m0 - mnew);
            l0 = l0*scl + sum; m0 = mnew;
            if(hf==0) ((float*)(smem+RSC))[row] = scl;
            bf* pph = (bf*)(smem + UOFF + row*560) + hf*64;
            bf* ppl = (bf*)(smem + UOFF + row*560 + 256) + hf*64;
            #pragma unroll
            for(int i=0;i<64;i++) splitw(sv[i], pph+i, ppl+i);
        }
        __syncthreads();

        {
            float s0 = ((float*)(smem+RSC))[16*w + gid];
            float s1 = ((float*)(smem+RSC))[16*w + gid + 8];
            #pragma unroll
            for(int j=0;j<8;j++){ occ[j][0]*=s0; occ[j][1]*=s0; occ[j][2]*=s1; occ[j][3]*=s1; }
            #pragma unroll
            for(int ch=0;ch<8;ch++){
                uint32_t pa = sb + UOFF + (uint32_t)((16*w + (lane&15))*560)
                              + (uint32_t)(ch*32) + (uint32_t)(((lane>>4)&1)<<4);
                uint32_t ph_[4], pl_[4];
                ldm_x4(ph_, pa);
                ldm_x4(pl_, pa + 256u);
                uint32_t vbh[8][2], vbl[8][2];
                #pragma unroll
                for(int jp=0;jp<4;jp++){
                    int nr = jp*16 + (lane&7) + (((lane>>4)&1)<<3);
                    uint32_t cb = (uint32_t)(((lane>>3)&1)<<4);
                    uint32_t ad = sb + VOFF + (uint32_t)(nr*272) + (uint32_t)(ch*32) + cb;
                    ldm_x4(&vbh[2*jp][0], ad);
                    ldm_x4(&vbl[2*jp][0], ad + 17408u);
                }
                #pragma unroll
                for(int j=0;j<8;j++){
                    mma_bf(occ[j], ph_, vbh[j]);
                    mma_bf(occ[j], ph_, vbl[j]);
                    mma_bf(occ[j], pl_, vbh[j]);
                }
            }
        }
        __syncthreads();
        if(kb+1 < NKB) loadV(kb+1);
    }

    if((tid&1)==0) ((float*)(smem+RLI))[tid>>1] = 1.f/l0;
    __syncthreads();
    float li0 = ((float*)(smem+RLI))[16*w + gid];
    float li1 = ((float*)(smem+RLI))[16*w + gid + 8];
    #pragma unroll
    for(int j=0;j<8;j++){
        int col = h*KDH + j*8 + t4*2;
        long r0 = qrow0 + 16*w + gid;
        long r1 = r0 + 8;
        float a0 = occ[j][0]*li0, a1 = occ[j][1]*li0;
        float a2 = occ[j][2]*li1, a3 = occ[j][3]*li1;
        __nv_bfloat162 hp, lp;
        hp.x = __float2bfloat16(a0); hp.y = __float2bfloat16(a1);
        lp.x = __float2bfloat16(a0 - __bfloat162float(hp.x));
        lp.y = __float2bfloat16(a1 - __bfloat162float(hp.y));
        *(__nv_bfloat162*)(Oh + r0*KD + col) = hp;
        *(__nv_bfloat162*)(Ol + r0*KD + col) = lp;
        hp.x = __float2bfloat16(a2); hp.y = __float2bfloat16(a3);
        lp.x = __float2bfloat16(a2 - __bfloat162float(hp.x));
        lp.y = __float2bfloat16(a3 - __bfloat162float(hp.y));
        *(__nv_bfloat162*)(Oh + r1*KD + col) = hp;
        *(__nv_bfloat162*)(Ol + r1*KD + col) = lp;
    }
}

// ---------------- split-bf16 HMMA GEMM (NT) ----------------
template<int BN>
__global__ void __launch_bounds__(256)
gemm_mma(const bf* __restrict__ Ah, const bf* __restrict__ Al,
         const bf* __restrict__ Bh, const bf* __restrict__ Bl,
         const float* __restrict__ bias, int biasMode, const float* __restrict__ Res,
         float* __restrict__ Cf, bf* __restrict__ Ch, bf* __restrict__ Cl, int doGate,
         int K, int lda, int ldb, int ldc,
         int Hn, long sAb, long sAh2, long sBb, long sBh2, long sCb, long sCh2,
         float alpha)
{
    extern __shared__ char smem[];
    const int tid = threadIdx.x, lane = tid&31, w = tid>>5;
    const int wm = w&1, wn = w>>1;
    const int gid = lane>>2, t4 = lane&3;
    constexpr int NT = BN/32;
    constexpr int BW = BN/64;
    constexpr int SS = 20480 + BN*160;

    int z = blockIdx.z, zb = z/Hn, zh = z - zb*Hn;
    long coff = (long)zb*sCb + (long)zh*sCh2;
    Ah += (long)zb*sAb + (long)zh*sAh2; Al += (long)zb*sAb + (long)zh*sAh2;
    Bh += (long)zb*sBb + (long)zh*sBh2; Bl += (long)zb*sBb + (long)zh*sBh2;

    const int row0 = blockIdx.y << 7;
    const int col0 = blockIdx.x * BN;
    uint32_t sb = cvsm(smem);
    int nch = K >> 5;

    float cc[4][NT][4];
    #pragma unroll
    for(int i=0;i<4;i++)
        #pragma unroll
        for(int j=0;j<NT;j++)
            #pragma unroll
            for(int q=0;q<4;q++) cc[i][j][q]=0.f;

    auto issue = [&](int kc){
        uint32_t bufb = sb + (uint32_t)(kc&1)*SS;
        int k0 = kc<<5;
        #pragma unroll
        for(int i=0;i<2;i++){
            int wd = tid + (i<<8); int r = wd>>2, wi = wd&3;
            uint32_t so = bufb + (uint32_t)(r*80 + wi*16);
            long go = (long)(row0+r)*lda + k0 + (wi<<3);
            CPA(so,         Ah+go);
            CPA(so + 10240, Al+go);
        }
        #pragma unroll
        for(int i=0;i<BW;i++){
            int wd = tid + (i<<8); int r = wd>>2, wi = wd&3;
            uint32_t so = bufb + 20480u + (uint32_t)(r*80 + wi*16);
            long go = (long)(col0+r)*ldb + k0 + (wi<<3);
            CPA(so,           Bh+go);
            CPA(so + BN*80u,  Bl+go);
        }
        CPA_COMMIT();
    };

    issue(0);
    for(int kc=0; kc<nch; kc++){
        if(kc+1 < nch){ issue(kc+1); CPA_WAIT1(); }
        else          { CPA_WAIT0(); }
        __syncthreads();
        uint32_t bufb = sb + (uint32_t)(kc&1)*SS;
        #pragma unroll
        for(int ks=0; ks<2; ks++){
            uint32_t bh[NT][2], bl[NT][2];
            #pragma unroll
            for(int jp=0; jp<NT/2; jp++){
                int nr = wn*(BN/4) + jp*16 + (lane&7) + (((lane>>4)&1)<<3);
                uint32_t cb = (uint32_t)(((lane>>3)&1)<<4);
                uint32_t ad = bufb + 20480u + (uint32_t)(nr*80) + (uint32_t)(ks*32) + cb;
                ldm_x4(&bh[2*jp][0], ad);
                ldm_x4(&bl[2*jp][0], ad + BN*80u);
            }
            #pragma unroll
            for(int mt=0; mt<4; mt++){
                int ar = wm*64 + mt*16 + (lane&15);
                uint32_t cb = (uint32_t)(((lane>>4)&1)<<4);
                uint32_t ad = bufb + (uint32_t)(ar*80) + (uint32_t)(ks*32) + cb;
                uint32_t ah[4], al[4];
                ldm_x4(ah, ad);
                ldm_x4(al, ad + 10240u);
                #pragma unroll
                for(int j=0; j<NT; j++){
                    mma_bf(cc[mt][j], ah, bh[j]);
                    mma_bf(cc[mt][j], ah, bl[j]);
                    mma_bf(cc[mt][j], al, bh[j]);
                }
            }
        }
        __syncthreads();
    }

    #pragma unroll
    for(int mt=0;mt<4;mt++){
        #pragma unroll
        for(int j=0;j<NT;j++){
            int gn = col0 + wn*(BN/4) + j*8 + t4*2;
            #pragma unroll
            for(int h=0;h<2;h++){
                int gm = row0 + wm*64 + mt*16 + gid + 8*h;
                float v0 = cc[mt][j][2*h+0]*alpha;
                float v1 = cc[mt][j][2*h+1]*alpha;
                if(biasMode==1){ v0 += bias[gn]; v1 += bias[gn+1]; }
                else if(biasMode==2){ float bb = bias[gm]; v0 += bb; v1 += bb; }
                if(doGate){
                    float g = (v0/(1.f+__expf(-v0)))*v1;
                    long cr = (long)gm*ldc + (gn>>1);
                    splitw(g, Ch+cr, Cl+cr);
                } else {
                    long cr = (long)gm*ldc + coff + gn;
                    if(Res){ float2 rr = *(const float2*)(Res+cr); v0 += rr.x; v1 += rr.y; }
                    if(Cf){ float2 o; o.x=v0; o.y=v1; *(float2*)(Cf+cr) = o; }
                    if(Ch){
                        __nv_bfloat162 hp, lp;
                        hp.x = __float2bfloat16(v0); hp.y = __float2bfloat16(v1);
                        lp.x = __float2bfloat16(v0 - __bfloat162float(hp.x));
                        lp.y = __float2bfloat16(v1 - __bfloat162float(hp.y));
                        *(__nv_bfloat162*)(Ch+cr) = hp;
                        *(__nv_bfloat162*)(Cl+cr) = lp;
                    }
                }
            }
        }
    }
}

// ---------------- host ----------------
static void ltc(const bf* Ah, const bf* Al, const bf* Bh, const bf* Bl,
                const float* bias, int bMode, const float* Res,
                float* Cf, bf* Ch, bf* Cl, int doGate,
                int M, int N, int K, int lda, int ldb, int ldc,
                int Z, int Hn, long sAb, long sAh, long sBb, long sBh, long sCb, long sCh,
                float alpha)
{
    int smem = 2*(20480 + 128*160);
    cudaFuncSetAttribute(gemm_mma<128>, cudaFuncAttributeMaxDynamicSharedMemorySize, smem);
    dim3 g(N/128, M/128, Z);
    gemm_mma<128><<<g, 256, smem>>>(Ah,Al,Bh,Bl,bias,bMode,Res,Cf,Ch,Cl,doGate,
                                    K,lda,ldb,ldc,Hn,sAb,sAh,sBb,sBh,sCb,sCh,alpha);
}
#define SYM(T,v,s) T* v; { void* p_; cudaGetSymbolAddress(&p_, s); v = (T*)p_; }

extern "C" void kernel_launch(void* const* d_in, const int* in_sizes, int n_in,
                              void* d_out, int out_size)
{
    (void)in_sizes; (void)n_in; (void)out_size;
    const float* spatial   = (const float*)d_in[0];
    const float* temporal  = (const float*)d_in[1];
    const float* sLqg=(const float*)d_in[2],  *sLqb=(const float*)d_in[3];
    const float* sLkg=(const float*)d_in[4],  *sLkb=(const float*)d_in[5];
    const float* sWqkv=(const float*)d_in[6], *sBqkv=(const float*)d_in[7];
    const float* sWo=(const float*)d_in[8],   *sBo=(const float*)d_in[9];
    const float* sWp=(const float*)d_in[10],  *sBp=(const float*)d_in[11];
    const float* tLqg=(const float*)d_in[12], *tLqb=(const float*)d_in[13];
    const float* tLkg=(const float*)d_in[14], *tLkb=(const float*)d_in[15];
    const float* tWqkv=(const float*)d_in[16],*tBqkv=(const float*)d_in[17];
    const float* tWo=(const float*)d_in[18],  *tBo=(const float*)d_in[19];
    const float* tWp=(const float*)d_in[20],  *tBp=(const float*)d_in[21];
    const float* mLg=(const float*)d_in[22],  *mLb=(const float*)d_in[23];
    const float* mWin=(const float*)d_in[24], *mBin=(const float*)d_in[25];
    const float* mWout=(const float*)d_in[26],*mBout=(const float*)d_in[27];
    float* out = (float*)d_out;

    SYM(bf,lsqh,LsQh) SYM(bf,lsql,LsQl) SYM(bf,ltkh,LtKVh) SYM(bf,ltkl,LtKVl)
    SYM(bf,ltqh,LtQh) SYM(bf,ltql,LtQl) SYM(bf,lskh,LsKVh) SYM(bf,lskl,LsKVl)
    SYM(bf,qsh,Qsh) SYM(bf,qsl,Qsl) SYM(bf,ksh,Ksh) SYM(bf,ksl,Ksl)
    SYM(bf,vsh,VtSh) SYM(bf,vsl,VtSl) SYM(bf,qth,Qth) SYM(bf,qtl,Qtl)
    SYM(bf,kth,Kth) SYM(bf,ktl,Ktl) SYM(bf,vth,VtTh) SYM(bf,vtl,VtTl)
    SYM(bf,ash,AtSh) SYM(bf,asl,AtSl) SYM(bf,ath,AtTh) SYM(bf,atl,AtTl)
    SYM(float,sctx,SctxF) SYM(float,tctx,TctxF) SYM(float,tmn,TmeanF)
    SYM(bf,hmh,Hmh) SYM(bf,hml,Hml)
    SYM(bf,gth,Gth) SYM(bf,gtl,Gtl)
    SYM(bf,wqsh,WqkvSh) SYM(bf,wqsl,WqkvSl) SYM(bf,wqth,WqkvTh) SYM(bf,wqtl,WqkvTl)
    SYM(bf,wcsh,WcSh) SYM(bf,wcsl,WcSl) SYM(bf,wcth,WcTh) SYM(bf,wctl,WcTl)
    SYM(float,bcs,BcS) SYM(float,bct,BcT)
    SYM(bf,winh,Winh) SYM(bf,winl,Winl) SYM(bf,wouth,Wouth) SYM(bf,woutl,Woutl)
    SYM(float,binp,BinP)

    #define CV(src,dh,dl,dR,dC,sR,sC) conv_k<<<(int)(((long)(dR)*(dC)+255)/256),256>>>(src,dh,dl,dR,dC,sR,sC)
    CV(sWqkv,wqsh,wqsl,3*KD,KD,3*KD,KD);
    CV(tWqkv,wqth,wqtl,3*KD,KD,3*KD,KD);
    wc_k<<<(KD*KD+255)/256,256>>>(sWp, sWo, wcsh, wcsl);
    wc_k<<<(KD*KD+255)/256,256>>>(tWp, tWo, wcth, wctl);
    bc_k<<<2,256>>>(sWp, sBo, sBp, bcs);
    bc_k<<<2,256>>>(tWp, tBo, tBp, bct);
    convin_k<<<(int)(((long)NPAD*2*KD+255)/256),256>>>(mWin, winh, winl);
    CV(mWout,wouth,woutl,KD,KPAD,KD,KHID);
    padbin_k<<<(NPAD+255)/256,256>>>(mBin, binp);

    // fused LN pairs (shared row stats)
    ln2_k<<<SROWS,128>>>(spatial,  sLqg,sLqb, tLkg,tLkb, lsqh,lsql, lskh,lskl);
    ln2_k<<<TROWS,128>>>(temporal, sLkg,sLkb, tLqg,tLqb, ltkh,ltkl, ltqh,ltql);

    // projections
    ltc(lsqh,lsql, wqsh,wqsl, sBqkv,1,0, 0,qsh,qsl,0, SROWS,KD,KD, KD,KD,KD, 1,1,0,0,0,0,0,0, 1.f);
    ltc(ltkh,ltkl, wqsh+KD*KD,wqsl+KD*KD, sBqkv+KD,1,0, 0,ksh,ksl,0, TROWS,KD,KD, KD,KD,KD, 1,1,0,0,0,0,0,0, 1.f);
    ltc(wqsh+2*KD*KD,wqsl+2*KD*KD, ltkh,ltkl, sBqkv+2*KD,2,0, 0,vsh,vsl,0, KD,KNT,KD, KD,KD,KNT,
        KB,1, 0,0, (long)KNT*KD,0, (long)KD*KNT,0, 1.f);
    ltc(ltqh,ltql, wqth,wqtl, tBqkv,1,0, 0,qth,qtl,0, TROWS,KD,KD, KD,KD,KD, 1,1,0,0,0,0,0,0, 1.f);
    ltc(lskh,lskl, wqth+KD*KD,wqtl+KD*KD, tBqkv+KD,1,0, 0,kth,ktl,0, SROWS,KD,KD, KD,KD,KD, 1,1,0,0,0,0,0,0, 1.f);
    ltc(wqth+2*KD*KD,wqtl+2*KD*KD, lskh,lskl, tBqkv+2*KD,2,0, 0,vth,vtl,0, KD,KNS,KD, KD,KD,KNS,
        KB,1, 0,0, (long)KNS*KD,0, (long)KD*KNS,0, 1.f);

    // fused attention
    {
        int fsm = 218112;
        cudaFuncSetAttribute(flash_k, cudaFuncAttributeMaxDynamicSharedMemorySize, fsm);
        dim3 gs(1, KNS/128, KB*KH);
        flash_k<<<gs, 256, fsm>>>(qsh,qsl, ksh,ksl, vsh,vsl, ash,asl, KNS, KNT);
        dim3 gt(1, KNT/128, KB*KH);
        flash_k<<<gt, 256, fsm>>>(qth,qtl, kth,ktl, vth,vtl, ath,atl, KNT, KNS);
    }

    // combined output projection: ctx = attn @ Wc^T + bc + residual
    ltc(ash,asl, wcsh,wcsl, bcs,1,spatial,  sctx,0,0,0, SROWS,KD,KD, KD,KD,KD, 1,1,0,0,0,0,0,0, 1.f);
    ltc(ath,atl, wcth,wctl, bct,1,temporal, tctx,0,0,0, TROWS,KD,KD, KD,KD,KD, 1,1,0,0,0,0,0,0, 1.f);

    // mix
    tmean_k<<<(KB*KD+127)/128,128>>>(tctx, tmn);
    mixln_k<<<SROWS,128>>>(sctx, tmn, mLg, mLb, hmh, hml);
    ltc(hmh,hml, winh,winl, binp,1,0, 0,gth,gtl,1, SROWS,NPAD,2*KD, 2*KD,2*KD,KPAD, 1,1,0,0,0,0,0,0, 1.f);
    ltc(gth,gtl, wouth,woutl, mBout,1,sctx, out,0,0,0, SROWS,KD,KPAD, KPAD,KPAD,KD, 1,1,0,0,0,0,0,0, 1.f);
}

// round 11
// speedup vs baseline: 1.4096x; 1.4096x over previous
#include <cuda_runtime.h>
#include <cuda_fp16.h>
#include <math.h>
#include <stdint.h>

#define KD    512
#define KH    8
#define KDH   64
#define KHID  2730
#define KB    4
#define KNS   4096
#define KNT   512
#define SROWS (KB*KNS)
#define TROWS (KB*KNT)
#define KPAD  2752
#define NPAD  5504

typedef __half hf;
#define DEVH(n, s) __device__ __align__(16) hf n[s]
#define DEVF(n, s) __device__ __align__(16) float n[s]

// activations (A operands: hi+lo)
DEVH(LsQh,SROWS*KD); DEVH(LsQl,SROWS*KD);
DEVH(LtKVh,TROWS*KD);DEVH(LtKVl,TROWS*KD);
DEVH(LtQh,TROWS*KD); DEVH(LtQl,TROWS*KD);
DEVH(LsKVh,SROWS*KD);DEVH(LsKVl,SROWS*KD);
DEVH(Qsh,SROWS*KD);  DEVH(Qsl,SROWS*KD);
DEVH(Ksh,TROWS*KD);                    // K: B operand, hi only
DEVH(VtSh,KB*KD*KNT);                  // V: B operand, hi only
DEVH(Qth,TROWS*KD);  DEVH(Qtl,TROWS*KD);
DEVH(Kth,SROWS*KD);
DEVH(VtTh,KB*KD*KNS);
DEVH(AtSh,SROWS*KD); DEVH(AtSl,SROWS*KD);
DEVH(AtTh,TROWS*KD); DEVH(AtTl,TROWS*KD);
DEVH(H1Sh,SROWS*KD); DEVH(H1Sl,SROWS*KD);
DEVH(H1Th,TROWS*KD); DEVH(H1Tl,TROWS*KD);
DEVF(SctxF,SROWS*KD);
DEVF(TctxF,TROWS*KD);
DEVF(TmeanF,KB*KD);
DEVH(Hmh,SROWS*2*KD); DEVH(Hml,SROWS*2*KD);
DEVH(Gth,(size_t)SROWS*KPAD); DEVH(Gtl,(size_t)SROWS*KPAD);
// weights: Wqkv hi+lo (V-proj uses it as A); others hi only (B operands)
DEVH(WqkvSh,3*KD*KD); DEVH(WqkvSl,3*KD*KD);
DEVH(WqkvTh,3*KD*KD); DEVH(WqkvTl,3*KD*KD);
DEVH(WoSh,KD*KD); DEVH(WpSh,KD*KD);
DEVH(WoTh,KD*KD); DEVH(WpTh,KD*KD);
DEVH(Winh,NPAD*2*KD);
DEVH(Wouth,KD*KPAD);
DEVF(BinP,NPAD);

__device__ __forceinline__ void splitw(float x, hf* H, hf* L){
    hf h = __float2half(x); *H = h; *L = __float2half(x - __half2float(h));
}
__device__ __forceinline__ void mma_hf(float* c, const uint32_t* a, const uint32_t* b){
    asm volatile("mma.sync.aligned.m16n8k16.row.col.f32.f16.f16.f32 "
        "{%0,%1,%2,%3}, {%4,%5,%6,%7}, {%8,%9}, {%0,%1,%2,%3};"
        : "+f"(c[0]),"+f"(c[1]),"+f"(c[2]),"+f"(c[3])
        : "r"(a[0]),"r"(a[1]),"r"(a[2]),"r"(a[3]), "r"(b[0]),"r"(b[1]));
}
__device__ __forceinline__ uint32_t cvsm(const void* p){
    uint32_t a; asm("{ .reg .u64 t; cvta.to.shared.u64 t, %1; cvt.u32.u64 %0, t; }":"=r"(a):"l"(p)); return a;
}
__device__ __forceinline__ void ldm_x4(uint32_t* r, uint32_t a){
    asm volatile("ldmatrix.sync.aligned.m8n8.x4.shared.b16 {%0,%1,%2,%3}, [%4];"
        : "=r"(r[0]),"=r"(r[1]),"=r"(r[2]),"=r"(r[3]) : "r"(a));
}
#define CPA(d, s) asm volatile("cp.async.cg.shared.global [%0], [%1], 16;"::"r"(d),"l"(s):"memory")
#define CPA_COMMIT() asm volatile("cp.async.commit_group;":::"memory")
#define CPA_WAIT1() asm volatile("cp.async.wait_group 1;":::"memory")
#define CPA_WAIT0() asm volatile("cp.async.wait_group 0;":::"memory")

__device__ __forceinline__ float brSum(float v){
    __shared__ float sh[33]; __syncthreads();
    int ln = threadIdx.x&31, w = threadIdx.x>>5;
    #pragma unroll
    for(int o=16;o;o>>=1) v += __shfl_xor_sync(~0u,v,o);
    if(!ln) sh[w]=v; __syncthreads();
    if(!w){ int nw=blockDim.x>>5; float r=(ln<nw)?sh[ln]:0.f;
        #pragma unroll
        for(int o=16;o;o>>=1) r += __shfl_xor_sync(~0u,r,o);
        if(!ln) sh[32]=r; }
    __syncthreads(); return sh[32];
}

// ---------------- elementwise ----------------
__global__ void __launch_bounds__(128)
ln2_k(const float* __restrict__ x,
      const float* __restrict__ g1, const float* __restrict__ b1,
      const float* __restrict__ g2, const float* __restrict__ b2,
      hf* __restrict__ y1h, hf* __restrict__ y1l,
      hf* __restrict__ y2h, hf* __restrict__ y2l)
{
    long row = blockIdx.x;
    const float* px = x + row*KD;
    int t = threadIdx.x;
    float v[4]; float s=0.f;
    #pragma unroll
    for(int i=0;i<4;i++){ v[i]=px[t+(i<<7)]; s+=v[i]; }
    s = brSum(s); float m = s*(1.f/KD);
    float q=0.f;
    #pragma unroll
    for(int i=0;i<4;i++){ float d=v[i]-m; q+=d*d; }
    q = brSum(q); float inv = rsqrtf(q*(1.f/KD)+1e-5f);
    #pragma unroll
    for(int i=0;i<4;i++){
        int c=t+(i<<7);
        float xn = (v[i]-m)*inv;
        splitw(xn*g1[c]+b1[c], y1h+row*KD+c, y1l+row*KD+c);
        splitw(xn*g2[c]+b2[c], y2h+row*KD+c, y2l+row*KD+c);
    }
}

__global__ void __launch_bounds__(128)
mixln_k(const float* __restrict__ sc, const float* __restrict__ tm,
        const float* __restrict__ g, const float* __restrict__ b,
        hf* __restrict__ yh, hf* __restrict__ yl)
{
    int row = blockIdx.x, bb = row>>12;
    const float *ps = sc + (long)row*KD, *pm = tm + (long)bb*KD;
    hf *ph = yh + (long)row*2*KD, *pl = yl + (long)row*2*KD;
    int t = threadIdx.x;
    float v[8]; float s=0.f;
    #pragma unroll
    for(int i=0;i<8;i++){ int c=t+(i<<7); v[i]=(c<KD)?ps[c]:pm[c-KD]; s+=v[i]; }
    s = brSum(s); float m = s*(1.f/1024.f);
    float q=0.f;
    #pragma unroll
    for(int i=0;i<8;i++){ float d=v[i]-m; q+=d*d; }
    q = brSum(q); float inv = rsqrtf(q*(1.f/1024.f)+1e-5f);
    #pragma unroll
    for(int i=0;i<8;i++){ int c=t+(i<<7); splitw((v[i]-m)*inv*g[c]+b[c], ph+c, pl+c); }
}

__global__ void tmean_k(const float* __restrict__ tc, float* __restrict__ o)
{
    int i = blockIdx.x*blockDim.x + threadIdx.x;
    if(i >= KB*KD) return;
    int bb=i>>9, dd=i&511;
    const float* p = tc + (long)bb*KNT*KD + dd;
    float s=0.f;
    for(int t=0;t<KNT;t++) s += p[t*KD];
    o[i] = s*(1.f/KNT);
}

// hi+lo conversion (for Wqkv, used as A in V-proj)
__global__ void conv_k(const float* __restrict__ s, hf* __restrict__ dh, hf* __restrict__ dl,
                       int n)
{
    long i = (long)blockIdx.x*blockDim.x + threadIdx.x;
    if(i >= n) return;
    splitw(s[i], dh+i, dl+i);
}
// hi-only conversion with 2D zero pad (B-side weights)
__global__ void convb_k(const float* __restrict__ s, hf* __restrict__ dh,
                        int dR, int dC, int sR, int sC)
{
    long i = (long)blockIdx.x*blockDim.x + threadIdx.x;
    if(i >= (long)dR*dC) return;
    int r = (int)(i/dC), c = (int)(i - (long)r*dC);
    float v = (r<sR && c<sC) ? s[(long)r*sC + c] : 0.f;
    dh[i] = __float2half(v);
}
// Win interleave (hi only): dst row 2c+half = src row half*KHID+c
__global__ void convin_k(const float* __restrict__ s, hf* __restrict__ dh)
{
    long i = (long)blockIdx.x*blockDim.x + threadIdx.x;
    if(i >= (long)NPAD*2*KD) return;
    int r = (int)(i/(2*KD)), c = (int)(i - (long)r*(2*KD));
    int pair = r>>1, half = r&1;
    float v = (pair < KHID) ? s[(long)(half*KHID+pair)*(2*KD) + c] : 0.f;
    dh[i] = __float2half(v);
}
__global__ void padbin_k(const float* __restrict__ s, float* __restrict__ d)
{
    int i = blockIdx.x*blockDim.x + threadIdx.x;
    if(i >= NPAD) return;
    int pair = i>>1, half = i&1;
    d[i] = (pair < KHID) ? s[half*KHID + pair] : 0.f;
}

// ---------------- fused flash attention (fp16 2-chain HMMA) ----------------
// Q hi+lo; K,V hi only. smem: Q[0,36864) (hi 0,lo 18432, stride 144);
// K 2 bufs @36864 (18432 each); V @73728 (64x272=17408);
// U @91136 stride 560 (S fp32 [0,512) -> P hi [0,256) lo [256,512));
// RSC @162816, RLI @163328. Total 163840.
__global__ void __launch_bounds__(256)
flash_k(const hf* __restrict__ Qh, const hf* __restrict__ Ql,
        const hf* __restrict__ Kh, const hf* __restrict__ Vh,
        hf* __restrict__ Oh, hf* __restrict__ Ol,
        int Nq, int Nk)
{
    extern __shared__ char smem[];
    const int QOFF=0, KOFF=36864, VOFF=73728, UOFF=91136, RSC=162816, RLI=163328;
    const int tid = threadIdx.x, lane = tid&31, w = tid>>5;
    const int wm = w&1, wn = w>>1;
    const int gid = lane>>2, t4 = lane&3;
    uint32_t sb = cvsm(smem);

    int z = blockIdx.z, b = z>>3, h = z&7;
    long qrow0 = (long)b*Nq + (long)blockIdx.y*128;
    const hf* qh = Qh + qrow0*KD + h*KDH;
    const hf* ql = Ql + qrow0*KD + h*KDH;
    const hf* kh = Kh + (long)b*Nk*KD + h*KDH;
    const hf* vh = Vh + ((long)b*KD + h*KDH)*(long)Nk;

    #pragma unroll
    for(int i=0;i<4;i++){
        int wd = tid + (i<<8); int r = wd>>3, wi = wd&7;
        CPA(sb + QOFF + r*144 + wi*16,         qh + (long)r*KD + wi*8);
        CPA(sb + QOFF + 18432 + r*144 + wi*16, ql + (long)r*KD + wi*8);
    }
    CPA_COMMIT();

    int NKB = Nk >> 7;

    auto loadK = [&](int kb){
        uint32_t base = sb + KOFF + (uint32_t)(kb&1)*18432u;
        const hf* sh_ = kh + (long)kb*128*KD;
        #pragma unroll
        for(int i=0;i<4;i++){
            int wd = tid + (i<<8); int r = wd>>3, wi = wd&7;
            CPA(base + r*144 + wi*16, sh_ + (long)r*KD + wi*8);
        }
        CPA_COMMIT();
    };
    auto loadV = [&](int kb){
        #pragma unroll
        for(int i=0;i<4;i++){
            int wd = tid + (i<<8); int r = wd>>4, wi = wd&15;
            CPA(sb + VOFF + r*272 + wi*16, vh + (long)r*Nk + kb*128 + wi*8);
        }
        CPA_COMMIT();
    };
    loadK(0); loadV(0);

    float m0 = -1e30f, l0 = 0.f;
    float occ[8][4];
    #pragma unroll
    for(int j=0;j<8;j++){ occ[j][0]=0.f; occ[j][1]=0.f; occ[j][2]=0.f; occ[j][3]=0.f; }

    for(int kb=0; kb<NKB; kb++){
        CPA_WAIT0();
        __syncthreads();
        uint32_t Kb = sb + KOFF + (uint32_t)(kb&1)*18432u;

        // GEMM1: S = Q·K^T  (2 chains: qh·kh + ql·kh)
        float cc[4][4][4];
        #pragma unroll
        for(int i=0;i<4;i++)
            #pragma unroll
            for(int j=0;j<4;j++){ cc[i][j][0]=0.f; cc[i][j][1]=0.f; cc[i][j][2]=0.f; cc[i][j][3]=0.f; }
        #pragma unroll
        for(int kc=0;kc<4;kc++){
            uint32_t bh_[4][2];
            #pragma unroll
            for(int jp=0;jp<2;jp++){
                int nr = wn*32 + jp*16 + (lane&7) + (((lane>>4)&1)<<3);
                uint32_t cb = (uint32_t)(((lane>>3)&1)<<4);
                ldm_x4(&bh_[2*jp][0], Kb + (uint32_t)(nr*144) + (uint32_t)(kc*32) + cb);
            }
            #pragma unroll
            for(int mt=0;mt<4;mt++){
                int ar = wm*64 + mt*16 + (lane&15);
                uint32_t cb = (uint32_t)(((lane>>4)&1)<<4);
                uint32_t ad = sb + QOFF + (uint32_t)(ar*144) + (uint32_t)(kc*32) + cb;
                uint32_t ah[4], al[4];
                ldm_x4(ah, ad);
                ldm_x4(al, ad + 18432u);
                #pragma unroll
                for(int j=0;j<4;j++){
                    mma_hf(cc[mt][j], ah, bh_[j]);
                    mma_hf(cc[mt][j], al, bh_[j]);
                }
            }
        }
        #pragma unroll
        for(int mt=0;mt<4;mt++)
            #pragma unroll
            for(int j=0;j<4;j++){
                int col = wn*32 + j*8 + t4*2;
                int r0 = wm*64 + mt*16 + gid;
                float2 v0; v0.x = cc[mt][j][0]; v0.y = cc[mt][j][1];
                float2 v1; v1.x = cc[mt][j][2]; v1.y = cc[mt][j][3];
                *(float2*)(smem + UOFF + r0*560 + col*4)     = v0;
                *(float2*)(smem + UOFF + (r0+8)*560 + col*4) = v1;
            }
        if(kb+1 < NKB) loadK(kb+1);
        __syncthreads();

        // online softmax
        {
            int row = tid>>1, hfs = tid&1;
            const float* sp = (const float*)(smem + UOFF + row*560) + hfs*64;
            float sv[64]; float mx = -1e30f;
            #pragma unroll
            for(int i=0;i<64;i++){ sv[i] = sp[i]*0.125f; mx = fmaxf(mx, sv[i]); }
            mx = fmaxf(mx, __shfl_xor_sync(~0u, mx, 1));
            float mnew = fmaxf(m0, mx);
            float sum = 0.f;
            #pragma unroll
            for(int i=0;i<64;i++){ sv[i] = __expf(sv[i]-mnew); sum += sv[i]; }
            sum += __shfl_xor_sync(~0u, sum, 1);
            float scl = __expf(m0 - mnew);
            l0 = l0*scl + sum; m0 = mnew;
            if(hfs==0) ((float*)(smem+RSC))[row] = scl;
            hf* pph = (hf*)(smem + UOFF + row*560) + hfs*64;
            hf* ppl = (hf*)(smem + UOFF + row*560 + 256) + hfs*64;
            #pragma unroll
            for(int i=0;i<64;i++) splitw(sv[i], pph+i, ppl+i);
        }
        __syncthreads();

        // GEMM2: O = O*scale + P·V (2 chains: ph·vh + pl·vh)
        {
            float s0 = ((float*)(smem+RSC))[16*w + gid];
            float s1 = ((float*)(smem+RSC))[16*w + gid + 8];
            #pragma unroll
            for(int j=0;j<8;j++){ occ[j][0]*=s0; occ[j][1]*=s0; occ[j][2]*=s1; occ[j][3]*=s1; }
            #pragma unroll
            for(int ch=0;ch<8;ch++){
                uint32_t pa = sb + UOFF + (uint32_t)((16*w + (lane&15))*560)
                              + (uint32_t)(ch*32) + (uint32_t)(((lane>>4)&1)<<4);
                uint32_t ph_[4], pl_[4];
                ldm_x4(ph_, pa);
                ldm_x4(pl_, pa + 256u);
                uint32_t vbh[8][2];
                #pragma unroll
                for(int jp=0;jp<4;jp++){
                    int nr = jp*16 + (lane&7) + (((lane>>4)&1)<<3);
                    uint32_t cb = (uint32_t)(((lane>>3)&1)<<4);
                    ldm_x4(&vbh[2*jp][0], sb + VOFF + (uint32_t)(nr*272) + (uint32_t)(ch*32) + cb);
                }
                #pragma unroll
                for(int j=0;j<8;j++){
                    mma_hf(occ[j], ph_, vbh[j]);
                    mma_hf(occ[j], pl_, vbh[j]);
                }
            }
        }
        __syncthreads();
        if(kb+1 < NKB) loadV(kb+1);
    }

    if((tid&1)==0) ((float*)(smem+RLI))[tid>>1] = 1.f/l0;
    __syncthreads();
    float li0 = ((float*)(smem+RLI))[16*w + gid];
    float li1 = ((float*)(smem+RLI))[16*w + gid + 8];
    #pragma unroll
    for(int j=0;j<8;j++){
        int col = h*KDH + j*8 + t4*2;
        long r0 = qrow0 + 16*w + gid;
        long r1 = r0 + 8;
        float a0 = occ[j][0]*li0, a1 = occ[j][1]*li0;
        float a2 = occ[j][2]*li1, a3 = occ[j][3]*li1;
        __half2 hp, lp;
        hp.x = __float2half(a0); hp.y = __float2half(a1);
        lp.x = __float2half(a0 - __half2float(hp.x));
        lp.y = __float2half(a1 - __half2float(hp.y));
        *(__half2*)(Oh + r0*KD + col) = hp;
        *(__half2*)(Ol + r0*KD + col) = lp;
        hp.x = __float2half(a2); hp.y = __float2half(a3);
        lp.x = __float2half(a2 - __half2float(hp.x));
        lp.y = __float2half(a3 - __half2float(hp.y));
        *(__half2*)(Oh + r1*KD + col) = hp;
        *(__half2*)(Ol + r1*KD + col) = lp;
    }
}

// ---------------- fp16 2-chain HMMA GEMM (NT) ----------------
// C[m,n] = alpha*sum_k (Ah+Al)[m,k]*Bh[n,k] (+bias)(+Res).
// smem/stage: A-hi 10240, A-lo 10240, B-hi BN*80. 2-stage.
template<int BN>
__global__ void __launch_bounds__(256)
gemm_mma(const hf* __restrict__ Ah, const hf* __restrict__ Al,
         const hf* __restrict__ Bh,
         const float* __restrict__ bias, int biasMode, const float* __restrict__ Res,
         float* __restrict__ Cf, hf* __restrict__ Ch, hf* __restrict__ Cl, int doGate,
         int K, int lda, int ldb, int ldc,
         int Hn, long sAb, long sAh2, long sBb, long sBh2, long sCb, long sCh2,
         float alpha)
{
    extern __shared__ char smem[];
    const int tid = threadIdx.x, lane = tid&31, w = tid>>5;
    const int wm = w&1, wn = w>>1;
    const int gid = lane>>2, t4 = lane&3;
    constexpr int NT = BN/32;
    constexpr int BW = BN/64;
    constexpr int SS = 20480 + BN*80;

    int z = blockIdx.z, zb = z/Hn, zh = z - zb*Hn;
    long coff = (long)zb*sCb + (long)zh*sCh2;
    Ah += (long)zb*sAb + (long)zh*sAh2; Al += (long)zb*sAb + (long)zh*sAh2;
    Bh += (long)zb*sBb + (long)zh*sBh2;

    const int row0 = blockIdx.y << 7;
    const int col0 = blockIdx.x * BN;
    uint32_t sb = cvsm(smem);
    int nch = K >> 5;

    float cc[4][NT][4];
    #pragma unroll
    for(int i=0;i<4;i++)
        #pragma unroll
        for(int j=0;j<NT;j++)
            #pragma unroll
            for(int q=0;q<4;q++) cc[i][j][q]=0.f;

    auto issue = [&](int kc){
        uint32_t bufb = sb + (uint32_t)(kc&1)*SS;
        int k0 = kc<<5;
        #pragma unroll
        for(int i=0;i<2;i++){
            int wd = tid + (i<<8); int r = wd>>2, wi = wd&3;
            uint32_t so = bufb + (uint32_t)(r*80 + wi*16);
            long go = (long)(row0+r)*lda + k0 + (wi<<3);
            CPA(so,         Ah+go);
            CPA(so + 10240, Al+go);
        }
        #pragma unroll
        for(int i=0;i<BW;i++){
            int wd = tid + (i<<8); int r = wd>>2, wi = wd&3;
            uint32_t so = bufb + 20480u + (uint32_t)(r*80 + wi*16);
            long go = (long)(col0+r)*ldb + k0 + (wi<<3);
            CPA(so, Bh+go);
        }
        CPA_COMMIT();
    };

    issue(0);
    for(int kc=0; kc<nch; kc++){
        if(kc+1 < nch){ issue(kc+1); CPA_WAIT1(); }
        else          { CPA_WAIT0(); }
        __syncthreads();
        uint32_t bufb = sb + (uint32_t)(kc&1)*SS;
        #pragma unroll
        for(int ks=0; ks<2; ks++){
            uint32_t bh[NT][2];
            #pragma unroll
            for(int jp=0; jp<NT/2; jp++){
                int nr = wn*(BN/4) + jp*16 + (lane&7) + (((lane>>4)&1)<<3);
                uint32_t cb = (uint32_t)(((lane>>3)&1)<<4);
                ldm_x4(&bh[2*jp][0], bufb + 20480u + (uint32_t)(nr*80) + (uint32_t)(ks*32) + cb);
            }
            #pragma unroll
            for(int mt=0; mt<4; mt++){
                int ar = wm*64 + mt*16 + (lane&15);
                uint32_t cb = (uint32_t)(((lane>>4)&1)<<4);
                uint32_t ad = bufb + (uint32_t)(ar*80) + (uint32_t)(ks*32) + cb;
                uint32_t ah[4], al[4];
                ldm_x4(ah, ad);
                ldm_x4(al, ad + 10240u);
                #pragma unroll
                for(int j=0; j<NT; j++){
                    mma_hf(cc[mt][j], ah, bh[j]);
                    mma_hf(cc[mt][j], al, bh[j]);
                }
            }
        }
        __syncthreads();
    }

    #pragma unroll
    for(int mt=0;mt<4;mt++){
        #pragma unroll
        for(int j=0;j<NT;j++){
            int gn = col0 + wn*(BN/4) + j*8 + t4*2;
            #pragma unroll
            for(int h=0;h<2;h++){
                int gm = row0 + wm*64 + mt*16 + gid + 8*h;
                float v0 = cc[mt][j][2*h+0]*alpha;
                float v1 = cc[mt][j][2*h+1]*alpha;
                if(biasMode==1){ v0 += bias[gn]; v1 += bias[gn+1]; }
                else if(biasMode==2){ float bb = bias[gm]; v0 += bb; v1 += bb; }
                if(doGate){
                    float g = (v0/(1.f+__expf(-v0)))*v1;
                    long cr = (long)gm*ldc + (gn>>1);
                    splitw(g, Ch+cr, Cl+cr);
                } else {
                    long cr = (long)gm*ldc + coff + gn;
                    if(Res){ float2 rr = *(const float2*)(Res+cr); v0 += rr.x; v1 += rr.y; }
                    if(Cf){ float2 o; o.x=v0; o.y=v1; *(float2*)(Cf+cr) = o; }
                    if(Ch){
                        __half2 hp;
                        hp.x = __float2half(v0); hp.y = __float2half(v1);
                        *(__half2*)(Ch+cr) = hp;
                        if(Cl){
                            __half2 lp;
                            lp.x = __float2half(v0 - __half2float(hp.x));
                            lp.y = __float2half(v1 - __half2float(hp.y));
                            *(__half2*)(Cl+cr) = lp;
                        }
                    }
                }
            }
        }
    }
}

// ---------------- host ----------------
static void ltc(const hf* Ah, const hf* Al, const hf* Bh,
                const float* bias, int bMode, const float* Res,
                float* Cf, hf* Ch, hf* Cl, int doGate,
                int M, int N, int K, int lda, int ldb, int ldc,
                int Z, int Hn, long sAb, long sAh, long sBb, long sBh, long sCb, long sCh,
                float alpha)
{
    int smem = 2*(20480 + 128*80);   // 61440
    cudaFuncSetAttribute(gemm_mma<128>, cudaFuncAttributeMaxDynamicSharedMemorySize, smem);
    dim3 g(N/128, M/128, Z);
    gemm_mma<128><<<g, 256, smem>>>(Ah,Al,Bh,bias,bMode,Res,Cf,Ch,Cl,doGate,
                                    K,lda,ldb,ldc,Hn,sAb,sAh,sBb,sBh,sCb,sCh,alpha);
}
#define SYM(T,v,s) T* v; { void* p_; cudaGetSymbolAddress(&p_, s); v = (T*)p_; }

extern "C" void kernel_launch(void* const* d_in, const int* in_sizes, int n_in,
                              void* d_out, int out_size)
{
    (void)in_sizes; (void)n_in; (void)out_size;
    const float* spatial   = (const float*)d_in[0];
    const float* temporal  = (const float*)d_in[1];
    const float* sLqg=(const float*)d_in[2],  *sLqb=(const float*)d_in[3];
    const float* sLkg=(const float*)d_in[4],  *sLkb=(const float*)d_in[5];
    const float* sWqkv=(const float*)d_in[6], *sBqkv=(const float*)d_in[7];
    const float* sWo=(const float*)d_in[8],   *sBo=(const float*)d_in[9];
    const float* sWp=(const float*)d_in[10],  *sBp=(const float*)d_in[11];
    const float* tLqg=(const float*)d_in[12], *tLqb=(const float*)d_in[13];
    const float* tLkg=(const float*)d_in[14], *tLkb=(const float*)d_in[15];
    const float* tWqkv=(const float*)d_in[16],*tBqkv=(const float*)d_in[17];
    const float* tWo=(const float*)d_in[18],  *tBo=(const float*)d_in[19];
    const float* tWp=(const float*)d_in[20],  *tBp=(const float*)d_in[21];
    const float* mLg=(const float*)d_in[22],  *mLb=(const float*)d_in[23];
    const float* mWin=(const float*)d_in[24], *mBin=(const float*)d_in[25];
    const float* mWout=(const float*)d_in[26],*mBout=(const float*)d_in[27];
    float* out = (float*)d_out;

    SYM(hf,lsqh,LsQh) SYM(hf,lsql,LsQl) SYM(hf,ltkh,LtKVh) SYM(hf,ltkl,LtKVl)
    SYM(hf,ltqh,LtQh) SYM(hf,ltql,LtQl) SYM(hf,lskh,LsKVh) SYM(hf,lskl,LsKVl)
    SYM(hf,qsh,Qsh) SYM(hf,qsl,Qsl) SYM(hf,ksh,Ksh)
    SYM(hf,vsh,VtSh) SYM(hf,qth,Qth) SYM(hf,qtl,Qtl)
    SYM(hf,kth,Kth) SYM(hf,vth,VtTh)
    SYM(hf,ash,AtSh) SYM(hf,asl,AtSl) SYM(hf,ath,AtTh) SYM(hf,atl,AtTl)
    SYM(hf,h1sh,H1Sh) SYM(hf,h1sl,H1Sl) SYM(hf,h1th,H1Th) SYM(hf,h1tl,H1Tl)
    SYM(float,sctx,SctxF) SYM(float,tctx,TctxF) SYM(float,tmn,TmeanF)
    SYM(hf,hmh,Hmh) SYM(hf,hml,Hml)
    SYM(hf,gth,Gth) SYM(hf,gtl,Gtl)
    SYM(hf,wqsh,WqkvSh) SYM(hf,wqsl,WqkvSl) SYM(hf,wqth,WqkvTh) SYM(hf,wqtl,WqkvTl)
    SYM(hf,wosh,WoSh) SYM(hf,wpsh,WpSh) SYM(hf,woth,WoTh) SYM(hf,wpth,WpTh)
    SYM(hf,winh,Winh) SYM(hf,wouth,Wouth)
    SYM(float,binp,BinP)

    // weight conversions
    conv_k<<<(3*KD*KD+255)/256,256>>>(sWqkv, wqsh, wqsl, 3*KD*KD);
    conv_k<<<(3*KD*KD+255)/256,256>>>(tWqkv, wqth, wqtl, 3*KD*KD);
    convb_k<<<(KD*KD+255)/256,256>>>(sWo, wosh, KD,KD,KD,KD);
    convb_k<<<(KD*KD+255)/256,256>>>(sWp, wpsh, KD,KD,KD,KD);
    convb_k<<<(KD*KD+255)/256,256>>>(tWo, woth, KD,KD,KD,KD);
    convb_k<<<(KD*KD+255)/256,256>>>(tWp, wpth, KD,KD,KD,KD);
    convin_k<<<(int)(((long)NPAD*2*KD+255)/256),256>>>(mWin, winh);
    convb_k<<<(int)(((long)KD*KPAD+255)/256),256>>>(mWout, wouth, KD,KPAD,KD,KHID);
    padbin_k<<<(NPAD+255)/256,256>>>(mBin, binp);

    // fused LN pairs (shared row stats)
    ln2_k<<<SROWS,128>>>(spatial,  sLqg,sLqb, tLkg,tLkb, lsqh,lsql, lskh,lskl);
    ln2_k<<<TROWS,128>>>(temporal, sLkg,sLkb, tLqg,tLqb, ltkh,ltkl, ltqh,ltql);

    // projections (Q: hi+lo out; K,V: hi only)
    ltc(lsqh,lsql, wqsh, sBqkv,1,0, 0,qsh,qsl,0, SROWS,KD,KD, KD,KD,KD, 1,1,0,0,0,0,0,0, 1.f);
    ltc(ltkh,ltkl, wqsh+KD*KD, sBqkv+KD,1,0, 0,ksh,0,0, TROWS,KD,KD, KD,KD,KD, 1,1,0,0,0,0,0,0, 1.f);
    ltc(wqsh+2*KD*KD,wqsl+2*KD*KD, ltkh, sBqkv+2*KD,2,0, 0,vsh,0,0, KD,KNT,KD, KD,KD,KNT,
        KB,1, 0,0, (long)KNT*KD,0, (long)KD*KNT,0, 1.f);
    ltc(ltqh,ltql, wqth, tBqkv,1,0, 0,qth,qtl,0, TROWS,KD,KD, KD,KD,KD, 1,1,0,0,0,0,0,0, 1.f);
    ltc(lskh,lskl, wqth+KD*KD, tBqkv+KD,1,0, 0,kth,0,0, SROWS,KD,KD, KD,KD,KD, 1,1,0,0,0,0,0,0, 1.f);
    ltc(wqth+2*KD*KD,wqtl+2*KD*KD, lskh, tBqkv+2*KD,2,0, 0,vth,0,0, KD,KNS,KD, KD,KD,KNS,
        KB,1, 0,0, (long)KNS*KD,0, (long)KD*KNS,0, 1.f);

    // fused attention
    {
        int fsm = 163840;
        cudaFuncSetAttribute(flash_k, cudaFuncAttributeMaxDynamicSharedMemorySize, fsm);
        dim3 gs(1, KNS/128, KB*KH);
        flash_k<<<gs, 256, fsm>>>(qsh,qsl, ksh, vsh, ash,asl, KNS, KNT);
        dim3 gt(1, KNT/128, KB*KH);
        flash_k<<<gt, 256, fsm>>>(qth,qtl, kth, vth, ath,atl, KNT, KNS);
    }

    // output projections
    ltc(ash,asl, wosh, sBo,1,0, 0,h1sh,h1sl,0, SROWS,KD,KD, KD,KD,KD, 1,1,0,0,0,0,0,0, 1.f);
    ltc(h1sh,h1sl, wpsh, sBp,1,spatial, sctx,0,0,0, SROWS,KD,KD, KD,KD,KD, 1,1,0,0,0,0,0,0, 1.f);
    ltc(ath,atl, woth, tBo,1,0, 0,h1th,h1tl,0, TROWS,KD,KD, KD,KD,KD, 1,1,0,0,0,0,0,0, 1.f);
    ltc(h1th,h1tl, wpth, tBp,1,temporal, tctx,0,0,0, TROWS,KD,KD, KD,KD,KD, 1,1,0,0,0,0,0,0, 1.f);

    // mix
    tmean_k<<<(KB*KD+127)/128,128>>>(tctx, tmn);
    mixln_k<<<SROWS,128>>>(sctx, tmn, mLg, mLb, hmh, hml);
    ltc(hmh,hml, winh, binp,1,0, 0,gth,gtl,1, SROWS,NPAD,2*KD, 2*KD,2*KD,KPAD, 1,1,0,0,0,0,0,0, 1.f);
    ltc(gth,gtl, wouth, mBout,1,sctx, out,0,0,0, SROWS,KD,KPAD, KPAD,KPAD,KD, 1,1,0,0,0,0,0,0, 1.f);
}

// round 12
// speedup vs baseline: 2.2408x; 1.5896x over previous
#include <cuda_runtime.h>
#include <cuda_fp16.h>
#include <math.h>
#include <stdint.h>

#define KD    512
#define KH    8
#define KDH   64
#define KHID  2730
#define KB    4
#define KNS   4096
#define KNT   512
#define SROWS (KB*KNS)
#define TROWS (KB*KNT)
#define KPAD  2752
#define NPAD  5504

typedef __half hf;
#define DEVH(n, s) __device__ __align__(16) hf n[s]
#define DEVF(n, s) __device__ __align__(16) float n[s]

// activations (all fp16, single precision level)
DEVH(LsQ,SROWS*KD);
DEVH(LtKV,TROWS*KD);
DEVH(LtQ,TROWS*KD);
DEVH(LsKV,SROWS*KD);
DEVH(Qs,SROWS*KD);
DEVH(Ks,TROWS*KD);
DEVH(VtS,KB*KD*KNT);
DEVH(Qt,TROWS*KD);
DEVH(Kt,SROWS*KD);
DEVH(VtT,KB*KD*KNS);
DEVH(AtS,SROWS*KD);
DEVH(AtT,TROWS*KD);
DEVH(H1S,SROWS*KD);
DEVH(H1T,TROWS*KD);
DEVF(SctxF,SROWS*KD);
DEVF(TctxF,TROWS*KD);
DEVF(TmeanF,KB*KD);
DEVH(Hm,SROWS*2*KD);
DEVH(Gt,(size_t)SROWS*KPAD);
// weights (fp16)
DEVH(WqkvS,3*KD*KD);
DEVH(WqkvT,3*KD*KD);
DEVH(WoS,KD*KD); DEVH(WpS,KD*KD);
DEVH(WoT,KD*KD); DEVH(WpT,KD*KD);
DEVH(Win,NPAD*2*KD);
DEVH(Wout,KD*KPAD);
DEVF(BinP,NPAD);

__device__ __forceinline__ void mma_hf(float* c, const uint32_t* a, const uint32_t* b){
    asm volatile("mma.sync.aligned.m16n8k16.row.col.f32.f16.f16.f32 "
        "{%0,%1,%2,%3}, {%4,%5,%6,%7}, {%8,%9}, {%0,%1,%2,%3};"
        : "+f"(c[0]),"+f"(c[1]),"+f"(c[2]),"+f"(c[3])
        : "r"(a[0]),"r"(a[1]),"r"(a[2]),"r"(a[3]), "r"(b[0]),"r"(b[1]));
}
__device__ __forceinline__ uint32_t cvsm(const void* p){
    uint32_t a; asm("{ .reg .u64 t; cvta.to.shared.u64 t, %1; cvt.u32.u64 %0, t; }":"=r"(a):"l"(p)); return a;
}
__device__ __forceinline__ void ldm_x4(uint32_t* r, uint32_t a){
    asm volatile("ldmatrix.sync.aligned.m8n8.x4.shared.b16 {%0,%1,%2,%3}, [%4];"
        : "=r"(r[0]),"=r"(r[1]),"=r"(r[2]),"=r"(r[3]) : "r"(a));
}
#define CPA(d, s) asm volatile("cp.async.cg.shared.global [%0], [%1], 16;"::"r"(d),"l"(s):"memory")
#define CPA_COMMIT() asm volatile("cp.async.commit_group;":::"memory")
#define CPA_WAIT1() asm volatile("cp.async.wait_group 1;":::"memory")
#define CPA_WAIT0() asm volatile("cp.async.wait_group 0;":::"memory")

__device__ __forceinline__ float brSum(float v){
    __shared__ float sh[33]; __syncthreads();
    int ln = threadIdx.x&31, w = threadIdx.x>>5;
    #pragma unroll
    for(int o=16;o;o>>=1) v += __shfl_xor_sync(~0u,v,o);
    if(!ln) sh[w]=v; __syncthreads();
    if(!w){ int nw=blockDim.x>>5; float r=(ln<nw)?sh[ln]:0.f;
        #pragma unroll
        for(int o=16;o;o>>=1) r += __shfl_xor_sync(~0u,r,o);
        if(!ln) sh[32]=r; }
    __syncthreads(); return sh[32];
}

// ---------------- elementwise ----------------
__global__ void __launch_bounds__(128)
ln2_k(const float* __restrict__ x,
      const float* __restrict__ g1, const float* __restrict__ b1,
      const float* __restrict__ g2, const float* __restrict__ b2,
      hf* __restrict__ y1, hf* __restrict__ y2)
{
    long row = blockIdx.x;
    const float* px = x + row*KD;
    int t = threadIdx.x;
    float v[4]; float s=0.f;
    #pragma unroll
    for(int i=0;i<4;i++){ v[i]=px[t+(i<<7)]; s+=v[i]; }
    s = brSum(s); float m = s*(1.f/KD);
    float q=0.f;
    #pragma unroll
    for(int i=0;i<4;i++){ float d=v[i]-m; q+=d*d; }
    q = brSum(q); float inv = rsqrtf(q*(1.f/KD)+1e-5f);
    #pragma unroll
    for(int i=0;i<4;i++){
        int c=t+(i<<7);
        float xn = (v[i]-m)*inv;
        y1[row*KD+c] = __float2half(xn*g1[c]+b1[c]);
        y2[row*KD+c] = __float2half(xn*g2[c]+b2[c]);
    }
}

__global__ void __launch_bounds__(128)
mixln_k(const float* __restrict__ sc, const float* __restrict__ tm,
        const float* __restrict__ g, const float* __restrict__ b,
        hf* __restrict__ y)
{
    int row = blockIdx.x, bb = row>>12;
    const float *ps = sc + (long)row*KD, *pm = tm + (long)bb*KD;
    hf *py = y + (long)row*2*KD;
    int t = threadIdx.x;
    float v[8]; float s=0.f;
    #pragma unroll
    for(int i=0;i<8;i++){ int c=t+(i<<7); v[i]=(c<KD)?ps[c]:pm[c-KD]; s+=v[i]; }
    s = brSum(s); float m = s*(1.f/1024.f);
    float q=0.f;
    #pragma unroll
    for(int i=0;i<8;i++){ float d=v[i]-m; q+=d*d; }
    q = brSum(q); float inv = rsqrtf(q*(1.f/1024.f)+1e-5f);
    #pragma unroll
    for(int i=0;i<8;i++){ int c=t+(i<<7); py[c] = __float2half((v[i]-m)*inv*g[c]+b[c]); }
}

__global__ void tmean_k(const float* __restrict__ tc, float* __restrict__ o)
{
    int i = blockIdx.x*blockDim.x + threadIdx.x;
    if(i >= KB*KD) return;
    int bb=i>>9, dd=i&511;
    const float* p = tc + (long)bb*KNT*KD + dd;
    float s=0.f;
    for(int t=0;t<KNT;t++) s += p[t*KD];
    o[i] = s*(1.f/KNT);
}

__global__ void convb_k(const float* __restrict__ s, hf* __restrict__ dh,
                        int dR, int dC, int sR, int sC)
{
    long i = (long)blockIdx.x*blockDim.x + threadIdx.x;
    if(i >= (long)dR*dC) return;
    int r = (int)(i/dC), c = (int)(i - (long)r*dC);
    float v = (r<sR && c<sC) ? s[(long)r*sC + c] : 0.f;
    dh[i] = __float2half(v);
}
__global__ void convin_k(const float* __restrict__ s, hf* __restrict__ dh)
{
    long i = (long)blockIdx.x*blockDim.x + threadIdx.x;
    if(i >= (long)NPAD*2*KD) return;
    int r = (int)(i/(2*KD)), c = (int)(i - (long)r*(2*KD));
    int pair = r>>1, half = r&1;
    float v = (pair < KHID) ? s[(long)(half*KHID+pair)*(2*KD) + c] : 0.f;
    dh[i] = __float2half(v);
}
__global__ void padbin_k(const float* __restrict__ s, float* __restrict__ d)
{
    int i = blockIdx.x*blockDim.x + threadIdx.x;
    if(i >= NPAD) return;
    int pair = i>>1, half = i&1;
    d[i] = (pair < KHID) ? s[half*KHID + pair] : 0.f;
}

// ---------------- fused flash attention (fp16 single-chain HMMA) ----------------
// smem: Q [0,18432) stride 144; K 2 bufs @18432 (18432 each);
// V @55296 (64x272=17408); U @72704 stride 560 (S fp32 [0,512) -> P hf [0,256));
// RSC @144384, RLI @144896. Total 145408.
__global__ void __launch_bounds__(256)
flash_k(const hf* __restrict__ Q, const hf* __restrict__ K,
        const hf* __restrict__ V, hf* __restrict__ O,
        int Nq, int Nk)
{
    extern __shared__ char smem[];
    const int QOFF=0, KOFF=18432, VOFF=55296, UOFF=72704, RSC=144384, RLI=144896;
    const int tid = threadIdx.x, lane = tid&31, w = tid>>5;
    const int wm = w&1, wn = w>>1;
    const int gid = lane>>2, t4 = lane&3;
    uint32_t sb = cvsm(smem);

    int z = blockIdx.z, b = z>>3, h = z&7;
    long qrow0 = (long)b*Nq + (long)blockIdx.y*128;
    const hf* qp = Q + qrow0*KD + h*KDH;
    const hf* kp = K + (long)b*Nk*KD + h*KDH;
    const hf* vp = V + ((long)b*KD + h*KDH)*(long)Nk;

    #pragma unroll
    for(int i=0;i<4;i++){
        int wd = tid + (i<<8); int r = wd>>3, wi = wd&7;
        CPA(sb + QOFF + r*144 + wi*16, qp + (long)r*KD + wi*8);
    }
    CPA_COMMIT();

    int NKB = Nk >> 7;

    auto loadK = [&](int kb){
        uint32_t base = sb + KOFF + (uint32_t)(kb&1)*18432u;
        const hf* s_ = kp + (long)kb*128*KD;
        #pragma unroll
        for(int i=0;i<4;i++){
            int wd = tid + (i<<8); int r = wd>>3, wi = wd&7;
            CPA(base + r*144 + wi*16, s_ + (long)r*KD + wi*8);
        }
        CPA_COMMIT();
    };
    auto loadV = [&](int kb){
        #pragma unroll
        for(int i=0;i<4;i++){
            int wd = tid + (i<<8); int r = wd>>4, wi = wd&15;
            CPA(sb + VOFF + r*272 + wi*16, vp + (long)r*Nk + kb*128 + wi*8);
        }
        CPA_COMMIT();
    };
    loadK(0); loadV(0);

    float m0 = -1e30f, l0 = 0.f;
    float occ[8][4];
    #pragma unroll
    for(int j=0;j<8;j++){ occ[j][0]=0.f; occ[j][1]=0.f; occ[j][2]=0.f; occ[j][3]=0.f; }

    for(int kb=0; kb<NKB; kb++){
        CPA_WAIT0();
        __syncthreads();
        uint32_t Kb = sb + KOFF + (uint32_t)(kb&1)*18432u;

        // GEMM1: S = Q·K^T (single chain)
        float cc[4][4][4];
        #pragma unroll
        for(int i=0;i<4;i++)
            #pragma unroll
            for(int j=0;j<4;j++){ cc[i][j][0]=0.f; cc[i][j][1]=0.f; cc[i][j][2]=0.f; cc[i][j][3]=0.f; }
        #pragma unroll
        for(int kc=0;kc<4;kc++){
            uint32_t bh_[4][2];
            #pragma unroll
            for(int jp=0;jp<2;jp++){
                int nr = wn*32 + jp*16 + (lane&7) + (((lane>>4)&1)<<3);
                uint32_t cb = (uint32_t)(((lane>>3)&1)<<4);
                ldm_x4(&bh_[2*jp][0], Kb + (uint32_t)(nr*144) + (uint32_t)(kc*32) + cb);
            }
            #pragma unroll
            for(int mt=0;mt<4;mt++){
                int ar = wm*64 + mt*16 + (lane&15);
                uint32_t cb = (uint32_t)(((lane>>4)&1)<<4);
                uint32_t ah[4];
                ldm_x4(ah, sb + QOFF + (uint32_t)(ar*144) + (uint32_t)(kc*32) + cb);
                #pragma unroll
                for(int j=0;j<4;j++) mma_hf(cc[mt][j], ah, bh_[j]);
            }
        }
        #pragma unroll
        for(int mt=0;mt<4;mt++)
            #pragma unroll
            for(int j=0;j<4;j++){
                int col = wn*32 + j*8 + t4*2;
                int r0 = wm*64 + mt*16 + gid;
                float2 v0; v0.x = cc[mt][j][0]; v0.y = cc[mt][j][1];
                float2 v1; v1.x = cc[mt][j][2]; v1.y = cc[mt][j][3];
                *(float2*)(smem + UOFF + r0*560 + col*4)     = v0;
                *(float2*)(smem + UOFF + (r0+8)*560 + col*4) = v1;
            }
        if(kb+1 < NKB) loadK(kb+1);
        __syncthreads();

        // online softmax
        {
            int row = tid>>1, hfs = tid&1;
            const float* sp = (const float*)(smem + UOFF + row*560) + hfs*64;
            float sv[64]; float mx = -1e30f;
            #pragma unroll
            for(int i=0;i<64;i++){ sv[i] = sp[i]*0.125f; mx = fmaxf(mx, sv[i]); }
            mx = fmaxf(mx, __shfl_xor_sync(~0u, mx, 1));
            float mnew = fmaxf(m0, mx);
            float sum = 0.f;
            #pragma unroll
            for(int i=0;i<64;i++){ sv[i] = __expf(sv[i]-mnew); sum += sv[i]; }
            sum += __shfl_xor_sync(~0u, sum, 1);
            float scl = __expf(m0 - mnew);
            l0 = l0*scl + sum; m0 = mnew;
            if(hfs==0) ((float*)(smem+RSC))[row] = scl;
            hf* pp = (hf*)(smem + UOFF + row*560) + hfs*64;
            #pragma unroll
            for(int i=0;i<64;i++) pp[i] = __float2half(sv[i]);
        }
        __syncthreads();

        // GEMM2: O = O*scale + P·V (single chain)
        {
            float s0 = ((float*)(smem+RSC))[16*w + gid];
            float s1 = ((float*)(smem+RSC))[16*w + gid + 8];
            #pragma unroll
            for(int j=0;j<8;j++){ occ[j][0]*=s0; occ[j][1]*=s0; occ[j][2]*=s1; occ[j][3]*=s1; }
            #pragma unroll
            for(int ch=0;ch<8;ch++){
                uint32_t pa = sb + UOFF + (uint32_t)((16*w + (lane&15))*560)
                              + (uint32_t)(ch*32) + (uint32_t)(((lane>>4)&1)<<4);
                uint32_t ph_[4];
                ldm_x4(ph_, pa);
                uint32_t vbh[8][2];
                #pragma unroll
                for(int jp=0;jp<4;jp++){
                    int nr = jp*16 + (lane&7) + (((lane>>4)&1)<<3);
                    uint32_t cb = (uint32_t)(((lane>>3)&1)<<4);
                    ldm_x4(&vbh[2*jp][0], sb + VOFF + (uint32_t)(nr*272) + (uint32_t)(ch*32) + cb);
                }
                #pragma unroll
                for(int j=0;j<8;j++) mma_hf(occ[j], ph_, vbh[j]);
            }
        }
        __syncthreads();
        if(kb+1 < NKB) loadV(kb+1);
    }

    if((tid&1)==0) ((float*)(smem+RLI))[tid>>1] = 1.f/l0;
    __syncthreads();
    float li0 = ((float*)(smem+RLI))[16*w + gid];
    float li1 = ((float*)(smem+RLI))[16*w + gid + 8];
    #pragma unroll
    for(int j=0;j<8;j++){
        int col = h*KDH + j*8 + t4*2;
        long r0 = qrow0 + 16*w + gid;
        long r1 = r0 + 8;
        __half2 p0, p1;
        p0.x = __float2half(occ[j][0]*li0); p0.y = __float2half(occ[j][1]*li0);
        p1.x = __float2half(occ[j][2]*li1); p1.y = __float2half(occ[j][3]*li1);
        *(__half2*)(O + r0*KD + col) = p0;
        *(__half2*)(O + r1*KD + col) = p1;
    }
}

// ---------------- fp16 single-chain HMMA GEMM (NT) ----------------
// C[m,n] = alpha*sum_k A[m,k]*B[n,k] (+bias)(+Res). smem/stage: A 10240 + B BN*80.
template<int BN>
__global__ void __launch_bounds__(256)
gemm_mma(const hf* __restrict__ A, const hf* __restrict__ B,
         const float* __restrict__ bias, int biasMode, const float* __restrict__ Res,
         float* __restrict__ Cf, hf* __restrict__ Ch, int doGate,
         int K, int lda, int ldb, int ldc,
         int Hn, long sAb, long sAh2, long sBb, long sBh2, long sCb, long sCh2,
         float alpha)
{
    extern __shared__ char smem[];
    const int tid = threadIdx.x, lane = tid&31, w = tid>>5;
    const int wm = w&1, wn = w>>1;
    const int gid = lane>>2, t4 = lane&3;
    constexpr int NT = BN/32;
    constexpr int BW = BN/64;
    constexpr int SS = 10240 + BN*80;

    int z = blockIdx.z, zb = z/Hn, zh = z - zb*Hn;
    long coff = (long)zb*sCb + (long)zh*sCh2;
    A += (long)zb*sAb + (long)zh*sAh2;
    B += (long)zb*sBb + (long)zh*sBh2;

    const int row0 = blockIdx.y << 7;
    const int col0 = blockIdx.x * BN;
    uint32_t sb = cvsm(smem);
    int nch = K >> 5;

    float cc[4][NT][4];
    #pragma unroll
    for(int i=0;i<4;i++)
        #pragma unroll
        for(int j=0;j<NT;j++)
            #pragma unroll
            for(int q=0;q<4;q++) cc[i][j][q]=0.f;

    auto issue = [&](int kc){
        uint32_t bufb = sb + (uint32_t)(kc&1)*SS;
        int k0 = kc<<5;
        #pragma unroll
        for(int i=0;i<2;i++){
            int wd = tid + (i<<8); int r = wd>>2, wi = wd&3;
            CPA(bufb + (uint32_t)(r*80 + wi*16), A + (long)(row0+r)*lda + k0 + (wi<<3));
        }
        #pragma unroll
        for(int i=0;i<BW;i++){
            int wd = tid + (i<<8); int r = wd>>2, wi = wd&3;
            CPA(bufb + 10240u + (uint32_t)(r*80 + wi*16), B + (long)(col0+r)*ldb + k0 + (wi<<3));
        }
        CPA_COMMIT();
    };

    issue(0);
    for(int kc=0; kc<nch; kc++){
        if(kc+1 < nch){ issue(kc+1); CPA_WAIT1(); }
        else          { CPA_WAIT0(); }
        __syncthreads();
        uint32_t bufb = sb + (uint32_t)(kc&1)*SS;
        #pragma unroll
        for(int ks=0; ks<2; ks++){
            uint32_t bh[NT][2];
            #pragma unroll
            for(int jp=0; jp<NT/2; jp++){
                int nr = wn*(BN/4) + jp*16 + (lane&7) + (((lane>>4)&1)<<3);
                uint32_t cb = (uint32_t)(((lane>>3)&1)<<4);
                ldm_x4(&bh[2*jp][0], bufb + 10240u + (uint32_t)(nr*80) + (uint32_t)(ks*32) + cb);
            }
            #pragma unroll
            for(int mt=0; mt<4; mt++){
                int ar = wm*64 + mt*16 + (lane&15);
                uint32_t cb = (uint32_t)(((lane>>4)&1)<<4);
                uint32_t ah[4];
                ldm_x4(ah, bufb + (uint32_t)(ar*80) + (uint32_t)(ks*32) + cb);
                #pragma unroll
                for(int j=0; j<NT; j++) mma_hf(cc[mt][j], ah, bh[j]);
            }
        }
        __syncthreads();
    }

    #pragma unroll
    for(int mt=0;mt<4;mt++){
        #pragma unroll
        for(int j=0;j<NT;j++){
            int gn = col0 + wn*(BN/4) + j*8 + t4*2;
            #pragma unroll
            for(int h=0;h<2;h++){
                int gm = row0 + wm*64 + mt*16 + gid + 8*h;
                float v0 = cc[mt][j][2*h+0]*alpha;
                float v1 = cc[mt][j][2*h+1]*alpha;
                if(biasMode==1){ v0 += bias[gn]; v1 += bias[gn+1]; }
                else if(biasMode==2){ float bb = bias[gm]; v0 += bb; v1 += bb; }
                if(doGate){
                    float g = (v0/(1.f+__expf(-v0)))*v1;
                    Ch[(long)gm*ldc + (gn>>1)] = __float2half(g);
                } else {
                    long cr = (long)gm*ldc + coff + gn;
                    if(Res){ float2 rr = *(const float2*)(Res+cr); v0 += rr.x; v1 += rr.y; }
                    if(Cf){ float2 o; o.x=v0; o.y=v1; *(float2*)(Cf+cr) = o; }
                    if(Ch){
                        __half2 hp; hp.x = __float2half(v0); hp.y = __float2half(v1);
                        *(__half2*)(Ch+cr) = hp;
                    }
                }
            }
        }
    }
}

// ---------------- host ----------------
static void ltc(const hf* A, const hf* B,
                const float* bias, int bMode, const float* Res,
                float* Cf, hf* Ch, int doGate,
                int M, int N, int K, int lda, int ldb, int ldc,
                int Z, int Hn, long sAb, long sAh, long sBb, long sBh, long sCb, long sCh,
                float alpha)
{
    int smem = 2*(10240 + 128*80);   // 40960
    cudaFuncSetAttribute(gemm_mma<128>, cudaFuncAttributeMaxDynamicSharedMemorySize, smem);
    dim3 g(N/128, M/128, Z);
    gemm_mma<128><<<g, 256, smem>>>(A,B,bias,bMode,Res,Cf,Ch,doGate,
                                    K,lda,ldb,ldc,Hn,sAb,sAh,sBb,sBh,sCb,sCh,alpha);
}
#define SYM(T,v,s) T* v; { void* p_; cudaGetSymbolAddress(&p_, s); v = (T*)p_; }

extern "C" void kernel_launch(void* const* d_in, const int* in_sizes, int n_in,
                              void* d_out, int out_size)
{
    (void)in_sizes; (void)n_in; (void)out_size;
    const float* spatial   = (const float*)d_in[0];
    const float* temporal  = (const float*)d_in[1];
    const float* sLqg=(const float*)d_in[2],  *sLqb=(const float*)d_in[3];
    const float* sLkg=(const float*)d_in[4],  *sLkb=(const float*)d_in[5];
    const float* sWqkv=(const float*)d_in[6], *sBqkv=(const float*)d_in[7];
    const float* sWo=(const float*)d_in[8],   *sBo=(const float*)d_in[9];
    const float* sWp=(const float*)d_in[10],  *sBp=(const float*)d_in[11];
    const float* tLqg=(const float*)d_in[12], *tLqb=(const float*)d_in[13];
    const float* tLkg=(const float*)d_in[14], *tLkb=(const float*)d_in[15];
    const float* tWqkv=(const float*)d_in[16],*tBqkv=(const float*)d_in[17];
    const float* tWo=(const float*)d_in[18],  *tBo=(const float*)d_in[19];
    const float* tWp=(const float*)d_in[20],  *tBp=(const float*)d_in[21];
    const float* mLg=(const float*)d_in[22],  *mLb=(const float*)d_in[23];
    const float* mWin=(const float*)d_in[24], *mBin=(const float*)d_in[25];
    const float* mWout=(const float*)d_in[26],*mBout=(const float*)d_in[27];
    float* out = (float*)d_out;

    SYM(hf,lsq,LsQ) SYM(hf,ltkv,LtKV) SYM(hf,ltq,LtQ) SYM(hf,lskv,LsKV)
    SYM(hf,qs,Qs) SYM(hf,ks,Ks) SYM(hf,vs,VtS)
    SYM(hf,qt,Qt) SYM(hf,kt,Kt) SYM(hf,vt,VtT)
    SYM(hf,as_,AtS) SYM(hf,at_,AtT)
    SYM(hf,h1s,H1S) SYM(hf,h1t,H1T)
    SYM(float,sctx,SctxF) SYM(float,tctx,TctxF) SYM(float,tmn,TmeanF)
    SYM(hf,hm,Hm) SYM(hf,gt,Gt)
    SYM(hf,wqs,WqkvS) SYM(hf,wqt,WqkvT)
    SYM(hf,wos,WoS) SYM(hf,wps,WpS) SYM(hf,wot,WoT) SYM(hf,wpt,WpT)
    SYM(hf,win,Win) SYM(hf,wout,Wout)
    SYM(float,binp,BinP)

    // weight conversions (all fp16)
    convb_k<<<(3*KD*KD+255)/256,256>>>(sWqkv, wqs, 3*KD,KD,3*KD,KD);
    convb_k<<<(3*KD*KD+255)/256,256>>>(tWqkv, wqt, 3*KD,KD,3*KD,KD);
    convb_k<<<(KD*KD+255)/256,256>>>(sWo, wos, KD,KD,KD,KD);
    convb_k<<<(KD*KD+255)/256,256>>>(sWp, wps, KD,KD,KD,KD);
    convb_k<<<(KD*KD+255)/256,256>>>(tWo, wot, KD,KD,KD,KD);
    convb_k<<<(KD*KD+255)/256,256>>>(tWp, wpt, KD,KD,KD,KD);
    convin_k<<<(int)(((long)NPAD*2*KD+255)/256),256>>>(mWin, win);
    convb_k<<<(int)(((long)KD*KPAD+255)/256),256>>>(mWout, wout, KD,KPAD,KD,KHID);
    padbin_k<<<(NPAD+255)/256,256>>>(mBin, binp);

    // fused LN pairs (shared row stats)
    ln2_k<<<SROWS,128>>>(spatial,  sLqg,sLqb, tLkg,tLkb, lsq, lskv);
    ln2_k<<<TROWS,128>>>(temporal, sLkg,sLkb, tLqg,tLqb, ltkv, ltq);

    // projections
    ltc(lsq, wqs, sBqkv,1,0, 0,qs,0, SROWS,KD,KD, KD,KD,KD, 1,1,0,0,0,0,0,0, 1.f);
    ltc(ltkv, wqs+KD*KD, sBqkv+KD,1,0, 0,ks,0, TROWS,KD,KD, KD,KD,KD, 1,1,0,0,0,0,0,0, 1.f);
    ltc(wqs+2*KD*KD, ltkv, sBqkv+2*KD,2,0, 0,vs,0, KD,KNT,KD, KD,KD,KNT,
        KB,1, 0,0, (long)KNT*KD,0, (long)KD*KNT,0, 1.f);
    ltc(ltq, wqt, tBqkv,1,0, 0,qt,0, TROWS,KD,KD, KD,KD,KD, 1,1,0,0,0,0,0,0, 1.f);
    ltc(lskv, wqt+KD*KD, tBqkv+KD,1,0, 0,kt,0, SROWS,KD,KD, KD,KD,KD, 1,1,0,0,0,0,0,0, 1.f);
    ltc(wqt+2*KD*KD, lskv, tBqkv+2*KD,2,0, 0,vt,0, KD,KNS,KD, KD,KD,KNS,
        KB,1, 0,0, (long)KNS*KD,0, (long)KD*KNS,0, 1.f);

    // fused attention
    {
        int fsm = 145408;
        cudaFuncSetAttribute(flash_k, cudaFuncAttributeMaxDynamicSharedMemorySize, fsm);
        dim3 gs(1, KNS/128, KB*KH);
        flash_k<<<gs, 256, fsm>>>(qs, ks, vs, as_, KNS, KNT);
        dim3 gt(1, KNT/128, KB*KH);
        flash_k<<<gt, 256, fsm>>>(qt, kt, vt, at_, KNT, KNS);
    }

    // output projections
    ltc(as_, wos, sBo,1,0, 0,h1s,0, SROWS,KD,KD, KD,KD,KD, 1,1,0,0,0,0,0,0, 1.f);
    ltc(h1s, wps, sBp,1,spatial, sctx,0,0, SROWS,KD,KD, KD,KD,KD, 1,1,0,0,0,0,0,0, 1.f);
    ltc(at_, wot, tBo,1,0, 0,h1t,0, TROWS,KD,KD, KD,KD,KD, 1,1,0,0,0,0,0,0, 1.f);
    ltc(h1t, wpt, tBp,1,temporal, tctx,0,0, TROWS,KD,KD, KD,KD,KD, 1,1,0,0,0,0,0,0, 1.f);

    // mix
    tmean_k<<<(KB*KD+127)/128,128>>>(tctx, tmn);
    mixln_k<<<SROWS,128>>>(sctx, tmn, mLg, mLb, hm);
    ltc(hm, win, binp,1,0, 0,gt,1, SROWS,NPAD,2*KD, 2*KD,2*KD,KPAD, 1,1,0,0,0,0,0,0, 1.f);
    ltc(gt, wout, mBout,1,sctx, out,0,0, SROWS,KD,KPAD, KPAD,KPAD,KD, 1,1,0,0,0,0,0,0, 1.f);
}